// round 5
// baseline (speedup 1.0000x reference)
#include <cuda_runtime.h>

// HoG layer, fused, with coalesced row staging:
//   input  x: (1, 3, 4096, 4096) f32 ; output feat: (511, 511, 36) f32
// Phase 1a: CTA loads rows {8cy+6, 8cy+7, 8cy+8} for each of 17 cell-rows,
//           densely (float4, 3 channels summed), into SMEM rowbuf.
// Phase 1b: one thread per cell extracts su/sl/sr/sd from rowbuf (LDS),
//           soft-bins into the 9-bin hist in SMEM.
// Phase 2:  2x2-cell block normalize, 36-float output per block (float4 STG).

#define IMG    4096
#define CELLS  512
#define OUTD   511
#define TC     16           // cells per tile side
#define HW     (TC + 1)     // 17: tile + halo
#define NCELL  (HW * HW)    // 289
#define NT     256
#define NSEG   34           // float4 segments per staged row (136 floats)
#define SEGW   (NSEG * 4)   // 136
#define NPOS   (HW * 3 * NSEG)   // 1734 float4 positions per CTA

__global__ __launch_bounds__(NT)
void hog_fused_kernel(const float* __restrict__ x, float* __restrict__ out)
{
    __shared__ float rowbuf[HW * 3 * SEGW];   // 6936 floats = 27744 B
    __shared__ float hist[NCELL * 9];         // 2601 floats = 10404 B

    const int cx0 = blockIdx.x * TC;
    const int cy0 = blockIdx.y * TC;
    const int tid = threadIdx.x;
    const long chs = (long)IMG * IMG;

    // Zero hist slots (same ownership as the fill below -> no barrier needed
    // between zero and fill; __syncthreads before phase 2 covers readers).
    for (int c = tid; c < NCELL; c += NT) {
        #pragma unroll
        for (int b = 0; b < 9; b++) hist[c * 9 + b] = 0.0f;
    }

    // ---- Phase 1a: coalesced staged load, channels summed ----
    // position i -> (lcy, r, seg): row = 8*(cy0+lcy)+6+r, colbase = 8*cx0+4+4*seg
    // 7 iterations per thread, batched 4 + 3 so loads overlap.
    const int colb0 = 8 * cx0 + 4;

    #pragma unroll
    for (int half = 0; half < 2; half++) {
        const int kbeg = (half == 0) ? 0 : 4;
        const int kend = (half == 0) ? 4 : 7;
        float4 va[4], vb[4], vc[4];
        int sts_off[4];
        #pragma unroll
        for (int k = kbeg; k < kend; k++) {
            const int i = tid + k * NT;
            const int lcy = i / (3 * NSEG);
            const int rem = i - lcy * (3 * NSEG);
            const int r   = rem / NSEG;
            const int seg = rem - r * NSEG;
            const int row = 8 * (cy0 + lcy) + 6 + r;
            const int col = colb0 + 4 * seg;
            const bool ok = (i < NPOS) && (row < IMG) && (col + 4 <= IMG);
            const float4 z = make_float4(0.f, 0.f, 0.f, 0.f);
            const float* p = x + (long)row * IMG + col;
            va[k - kbeg] = ok ? *(const float4*)(p)           : z;
            vb[k - kbeg] = ok ? *(const float4*)(p + chs)     : z;
            vc[k - kbeg] = ok ? *(const float4*)(p + 2 * chs) : z;
            sts_off[k - kbeg] = (lcy * 3 + r) * SEGW + 4 * seg;
        }
        #pragma unroll
        for (int k = kbeg; k < kend; k++) {
            const int j = k - kbeg;
            const int i = tid + k * NT;
            if (i < NPOS) {
                float4 s;
                s.x = va[j].x + vb[j].x + vc[j].x;
                s.y = va[j].y + vb[j].y + vc[j].y;
                s.z = va[j].z + vb[j].z + vc[j].z;
                s.w = va[j].w + vb[j].w + vc[j].w;
                *(float4*)&rowbuf[sts_off[j]] = s;
            }
        }
    }
    __syncthreads();

    // ---- Phase 1b: per-cell extraction + soft binning ----
    for (int c = tid; c < NCELL; c += NT) {
        const int lcy = c / HW;
        const int lcx = c - lcy * HW;
        const int cy = cy0 + lcy;
        const int cx = cx0 + lcx;
        if (cy >= CELLS || cx >= CELLS) continue;

        const float* rb = &rowbuf[(lcy * 3) * SEGW];
        const int xc = 8 * lcx + 3;             // col(px) within segment
        const float su = rb[xc];                // row py-1, col px
        const float sl = rb[SEGW + xc - 1];     // row py,   col px-1
        const float sr = rb[SEGW + xc + 1];     // row py,   col px+1 (0 if OOB)
        const float sd = rb[2 * SEGW + xc];     // row py+1, col px  (0 if OOB)

        const float gv = sd - su;
        const float gh = sr - sl;
        const float mag = sqrtf(gv * gv + gh * gh + 1e-6f);
        const float ang = fabsf(atanf(gh / (gv + 1e-9f)))
                          * (180.0f / 3.14159265358979323846f);

        // j = floor(ang/20 - 0.5), ang in [0, 90] -> j in [-1, 4]
        const float t  = ang * 0.05f;
        const int   ji = (int)floorf(t - 0.5f);
        const float vj  = mag * ((float)ji + 1.5f - t);
        const float vj1 = mag - vj;

        const int i0 = (ji < 0) ? 8 : ji;   // mod(ji, 9)
        const int i1 = ji + 1;              // in [0, 5], never == i0
        hist[c * 9 + i0] = vj;
        hist[c * 9 + i1] = vj1;
    }
    __syncthreads();

    // ---- Phase 2: one output block per thread ----
    const int ly = tid >> 4;
    const int lx = tid & 15;
    const int oy = cy0 + ly;
    const int ox = cx0 + lx;
    if (oy >= OUTD || ox >= OUTD) return;

    const float* h00 = &hist[(ly * HW + lx) * 9];
    const float* h01 = h00 + 9;
    const float* h10 = h00 + HW * 9;
    const float* h11 = h10 + 9;

    float blk[36];
    #pragma unroll
    for (int b = 0; b < 9; b++) {
        blk[b]      = h00[b];
        blk[9  + b] = h01[b];
        blk[18 + b] = h10[b];
        blk[27 + b] = h11[b];
    }

    float ss = 0.f;
    #pragma unroll
    for (int b = 0; b < 36; b++) ss += blk[b] * blk[b];
    const float inv = 1.0f / (sqrtf(ss) + 1e-9f);

    float4* o4 = reinterpret_cast<float4*>(out + ((size_t)oy * OUTD + ox) * 36);
    #pragma unroll
    for (int b = 0; b < 9; b++) {
        o4[b] = make_float4(blk[4 * b + 0] * inv,
                            blk[4 * b + 1] * inv,
                            blk[4 * b + 2] * inv,
                            blk[4 * b + 3] * inv);
    }
}

extern "C" void kernel_launch(void* const* d_in, const int* in_sizes, int n_in,
                              void* d_out, int out_size)
{
    const float* x = (const float*)d_in[0];
    float* out = (float*)d_out;
    dim3 grid(CELLS / TC, CELLS / TC);   // 32 x 32 tiles = 1024 CTAs
    hog_fused_kernel<<<grid, NT>>>(x, out);
}

// round 8
// speedup vs baseline: 1.0389x; 1.0389x over previous
#include <cuda_runtime.h>

// HoG layer, fused. Phase 1 = R3's scattered gather (2 cells/thread, 24 LDGs
// in flight). Phase 2 stages normalized blocks in SMEM, then writes them out
// as contiguous per-row runs -> 8x fewer store wavefronts.
// FIX vs R6: 16-byte alignment on shared arrays (float4 access on obuf).
//   input  x: (1, 3, 4096, 4096) f32 ; output feat: (511, 511, 36) f32

#define IMG   4096
#define CELLS 512
#define OUTD  511
#define TC    16          // cells per tile side
#define HW    (TC + 1)    // 17: tile + halo
#define NCELL (HW * HW)   // 289
#define NT    256

__global__ __launch_bounds__(NT)
void hog_fused_kernel(const float* __restrict__ x, float* __restrict__ out)
{
    __shared__ __align__(16) float obuf[NT * 36];     // 36864 B
    __shared__ __align__(16) float hist[NCELL * 9];   // 10404 B

    const int cx0 = blockIdx.x * TC;
    const int cy0 = blockIdx.y * TC;
    const int tid = threadIdx.x;
    const long chs = (long)IMG * IMG;

    // Zero hist slots this thread owns (same ownership as fill, no barrier).
    for (int c = tid; c < NCELL; c += NT) {
        #pragma unroll
        for (int b = 0; b < 9; b++) hist[c * 9 + b] = 0.0f;
    }

    // ---- Phase 1: two cells per thread, all loads issued up front ----
    float v[2][12];
    bool  valid[2];
    const float* base[2];
    bool  hd[2], hr[2];

    #pragma unroll
    for (int it = 0; it < 2; it++) {
        const int c = tid + it * NT;
        const int lcy = c / HW;
        const int lcx = c - lcy * HW;
        const int cy = cy0 + lcy;
        const int cx = cx0 + lcx;
        valid[it] = (c < NCELL) && (cy < CELLS) && (cx < CELLS);
        const int py = cy * 8 + 7;
        const int px = cx * 8 + 7;
        base[it] = x + (long)py * IMG + px;
        hd[it] = (py + 1 < IMG);
        hr[it] = (px + 1 < IMG);
    }

    #pragma unroll
    for (int it = 0; it < 2; it++) {
        const float* p = base[it];
        const bool va = valid[it];
        const bool vd = va && hd[it];
        const bool vr = va && hr[it];
        #pragma unroll
        for (int ch = 0; ch < 3; ch++) {
            const float* pc = p + ch * chs;
            v[it][ch * 4 + 0] = va ? pc[-IMG] : 0.0f;
            v[it][ch * 4 + 1] = va ? pc[-1]   : 0.0f;
            v[it][ch * 4 + 2] = vd ? pc[IMG]  : 0.0f;
            v[it][ch * 4 + 3] = vr ? pc[1]    : 0.0f;
        }
    }

    #pragma unroll
    for (int it = 0; it < 2; it++) {
        if (!valid[it]) continue;
        const float su = v[it][0] + v[it][4] + v[it][8];
        const float sl = v[it][1] + v[it][5] + v[it][9];
        const float sd = v[it][2] + v[it][6] + v[it][10];
        const float sr = v[it][3] + v[it][7] + v[it][11];

        const float gv = sd - su;
        const float gh = sr - sl;
        const float mag = sqrtf(gv * gv + gh * gh + 1e-6f);
        const float ang = fabsf(atanf(gh / (gv + 1e-9f)))
                          * (180.0f / 3.14159265358979323846f);

        const float t  = ang * 0.05f;                 // ang / 20
        const int   ji = (int)floorf(t - 0.5f);       // in [-1, 4]
        const float vj  = mag * ((float)ji + 1.5f - t);
        const float vj1 = mag - vj;

        const int i0 = (ji < 0) ? 8 : ji;   // mod(ji, 9)
        const int i1 = ji + 1;              // never == i0
        float* hrow = &hist[(tid + it * NT) * 9];
        hrow[i0] = vj;
        hrow[i1] = vj1;
    }
    __syncthreads();

    // ---- Phase 2a: normalize one block per thread into SMEM ----
    {
        const int ly = tid >> 4;
        const int lx = tid & 15;
        const float* h00 = &hist[(ly * HW + lx) * 9];
        const float* h01 = h00 + 9;
        const float* h10 = h00 + HW * 9;
        const float* h11 = h10 + 9;

        float blk[36];
        #pragma unroll
        for (int b = 0; b < 9; b++) {
            blk[b]      = h00[b];
            blk[9  + b] = h01[b];
            blk[18 + b] = h10[b];
            blk[27 + b] = h11[b];
        }

        float ss = 0.f;
        #pragma unroll
        for (int b = 0; b < 36; b++) ss += blk[b] * blk[b];
        const float inv = 1.0f / (sqrtf(ss) + 1e-9f);

        float4* o4 = reinterpret_cast<float4*>(&obuf[tid * 36]);
        #pragma unroll
        for (int b = 0; b < 9; b++) {
            o4[b] = make_float4(blk[4 * b + 0] * inv,
                                blk[4 * b + 1] * inv,
                                blk[4 * b + 2] * inv,
                                blk[4 * b + 3] * inv);
        }
    }
    __syncthreads();

    // ---- Phase 2b: coalesced copy SMEM -> GMEM, per block-row runs ----
    const int nbx = (cx0 + TC <= OUTD) ? TC : (OUTD - cx0);   // 16 or 15
    const int nby = (cy0 + TC <= OUTD) ? TC : (OUTD - cy0);
    const int row_f4 = nbx * 9;   // float4s per output row run (144 or 135)

    for (int r = 0; r < nby; r++) {
        const float4* src = reinterpret_cast<const float4*>(&obuf[r * TC * 36]);
        float4* dst = reinterpret_cast<float4*>(
            out + ((size_t)(cy0 + r) * OUTD + cx0) * 36);
        for (int i = tid; i < row_f4; i += NT) {
            dst[i] = src[i];
        }
    }
}

extern "C" void kernel_launch(void* const* d_in, const int* in_sizes, int n_in,
                              void* d_out, int out_size)
{
    const float* x = (const float*)d_in[0];
    float* out = (float*)d_out;
    dim3 grid(CELLS / TC, CELLS / TC);   // 32 x 32 tiles = 1024 CTAs
    hog_fused_kernel<<<grid, NT>>>(x, out);
}

// round 9
// speedup vs baseline: 1.0809x; 1.0405x over previous
#include <cuda_runtime.h>

// HoG layer, fused. Phase 1 = R3 scattered gather (2 cells/thread, 24 LDGs in
// flight, regs protected). Phase 2 = coalesced stores via SMEM staging, but
// CHUNKED (8 block-rows at a time) + register-light two-pass normalize so
// 5 CTAs/SM stay resident (R8 dropped to 4 and lost its ncu win to the tail).
//   input  x: (1, 3, 4096, 4096) f32 ; output feat: (511, 511, 36) f32

#define IMG   4096
#define CELLS 512
#define OUTD  511
#define TC    16          // cells per tile side
#define HW    (TC + 1)    // 17: tile + halo
#define NCELL (HW * HW)   // 289
#define NT    256
#define CR    8           // block-rows per phase-2 chunk
#define OBF4  (CR * TC * 9)   // float4s per chunk = 1152

__global__ __launch_bounds__(NT, 5)
void hog_fused_kernel(const float* __restrict__ x, float* __restrict__ out)
{
    __shared__ __align__(16) float obuf[CR * TC * 36];   // 18432 B
    __shared__ __align__(16) float hist[NCELL * 9];      // 10404 B

    const int cx0 = blockIdx.x * TC;
    const int cy0 = blockIdx.y * TC;
    const int tid = threadIdx.x;
    const long chs = (long)IMG * IMG;

    // Zero hist slots this thread owns (same ownership as fill, no barrier).
    for (int c = tid; c < NCELL; c += NT) {
        #pragma unroll
        for (int b = 0; b < 9; b++) hist[c * 9 + b] = 0.0f;
    }

    // ---- Phase 1: two cells per thread, all 24 loads issued up front ----
    float v[2][12];
    bool  valid[2];
    const float* base[2];
    bool  hd[2], hr[2];

    #pragma unroll
    for (int it = 0; it < 2; it++) {
        const int c = tid + it * NT;
        const int lcy = c / HW;
        const int lcx = c - lcy * HW;
        const int cy = cy0 + lcy;
        const int cx = cx0 + lcx;
        valid[it] = (c < NCELL) && (cy < CELLS) && (cx < CELLS);
        const int py = cy * 8 + 7;
        const int px = cx * 8 + 7;
        base[it] = x + (long)py * IMG + px;
        hd[it] = (py + 1 < IMG);
        hr[it] = (px + 1 < IMG);
    }

    #pragma unroll
    for (int it = 0; it < 2; it++) {
        const float* p = base[it];
        const bool va = valid[it];
        const bool vd = va && hd[it];
        const bool vr = va && hr[it];
        #pragma unroll
        for (int ch = 0; ch < 3; ch++) {
            const float* pc = p + ch * chs;
            v[it][ch * 4 + 0] = va ? pc[-IMG] : 0.0f;
            v[it][ch * 4 + 1] = va ? pc[-1]   : 0.0f;
            v[it][ch * 4 + 2] = vd ? pc[IMG]  : 0.0f;
            v[it][ch * 4 + 3] = vr ? pc[1]    : 0.0f;
        }
    }

    #pragma unroll
    for (int it = 0; it < 2; it++) {
        if (!valid[it]) continue;
        const float su = v[it][0] + v[it][4] + v[it][8];
        const float sl = v[it][1] + v[it][5] + v[it][9];
        const float sd = v[it][2] + v[it][6] + v[it][10];
        const float sr = v[it][3] + v[it][7] + v[it][11];

        const float gv = sd - su;
        const float gh = sr - sl;
        const float mag = sqrtf(gv * gv + gh * gh + 1e-6f);
        const float ang = fabsf(atanf(gh / (gv + 1e-9f)))
                          * (180.0f / 3.14159265358979323846f);

        const float t  = ang * 0.05f;                 // ang / 20
        const int   ji = (int)floorf(t - 0.5f);       // in [-1, 4]
        const float vj  = mag * ((float)ji + 1.5f - t);
        const float vj1 = mag - vj;

        const int i0 = (ji < 0) ? 8 : ji;   // mod(ji, 9)
        const int i1 = ji + 1;              // never == i0
        float* hrow = &hist[(tid + it * NT) * 9];
        hrow[i0] = vj;
        hrow[i1] = vj1;
    }
    __syncthreads();

    // ---- Phase 2: two chunks of 8 block-rows ----
    const int nbx = (cx0 + TC <= OUTD) ? TC : (OUTD - cx0);   // 16 or 15

    #pragma unroll
    for (int ck = 0; ck < 2; ck++) {
        const int oyb = cy0 + ck * CR;
        const int rows_c = (oyb + CR <= OUTD) ? CR : (OUTD - oyb); // 8 or 7

        // 2a: threads 0..127 normalize one block each (two-pass over hist,
        //     no 36-float register array).
        if (tid < CR * TC) {
            const int ly = ck * CR + (tid >> 4);
            const int lx = tid & 15;
            if ((oyb + (tid >> 4)) < OUTD && (cx0 + lx) < OUTD) {
                const float* hb = &hist[(ly * HW + lx) * 9];

                float ss = 0.f;
                #pragma unroll
                for (int s = 0; s < 4; s++) {
                    const float* h = hb + ((s & 1) ? 9 : 0) + ((s & 2) ? HW * 9 : 0);
                    #pragma unroll
                    for (int b = 0; b < 9; b++) ss += h[b] * h[b];
                }
                const float inv = 1.0f / (sqrtf(ss) + 1e-9f);

                float4* o4 = reinterpret_cast<float4*>(&obuf[tid * 36]);
                #pragma unroll
                for (int g = 0; g < 9; g++) {
                    float w[4];
                    #pragma unroll
                    for (int k = 0; k < 4; k++) {
                        const int i = 4 * g + k;          // 0..35
                        const int s = i / 9;              // segment (const)
                        const int b = i - s * 9;
                        w[k] = hb[((s & 1) ? 9 : 0) + ((s & 2) ? HW * 9 : 0) + b] * inv;
                    }
                    o4[g] = make_float4(w[0], w[1], w[2], w[3]);
                }
            }
        }
        __syncthreads();

        // 2b: coalesced copy SMEM -> GMEM
        if (rows_c == CR && nbx == TC) {
            // interior fast path: 1152 float4, flat
            const float4* src = reinterpret_cast<const float4*>(obuf);
            #pragma unroll
            for (int k = 0; k < (OBF4 + NT - 1) / NT; k++) {  // 5 iters, last partial
                const int f = tid + k * NT;
                if (f < OBF4) {
                    const int r = f / (TC * 9);               // row in chunk
                    const int i = f - r * (TC * 9);
                    float4* dst = reinterpret_cast<float4*>(
                        out + ((size_t)(oyb + r) * OUTD + cx0) * 36);
                    dst[i] = src[r * (TC * 9) + i];
                }
            }
        } else {
            const int row_f4 = nbx * 9;
            for (int r = 0; r < rows_c; r++) {
                const float4* src = reinterpret_cast<const float4*>(&obuf[r * TC * 36]);
                float4* dst = reinterpret_cast<float4*>(
                    out + ((size_t)(oyb + r) * OUTD + cx0) * 36);
                for (int i = tid; i < row_f4; i += NT) dst[i] = src[i];
            }
        }
        if (ck == 0) __syncthreads();   // obuf reused by chunk 1
    }
}

extern "C" void kernel_launch(void* const* d_in, const int* in_sizes, int n_in,
                              void* d_out, int out_size)
{
    const float* x = (const float*)d_in[0];
    float* out = (float*)d_out;
    dim3 grid(CELLS / TC, CELLS / TC);   // 32 x 32 tiles = 1024 CTAs
    hog_fused_kernel<<<grid, NT>>>(x, out);
}